// round 8
// baseline (speedup 1.0000x reference)
#include <cuda_runtime.h>
#include <cuda_bf16.h>

// Problem constants (from reference)
#define N_SAMPLES 65536
#define N_DIMS    128
#define K_NEG     10

constexpr int WARPS_PER_BLOCK = 16;
constexpr int THREADS = WARPS_PER_BLOCK * 32;          // 512
constexpr int NBLOCKS = N_SAMPLES / WARPS_PER_BLOCK;   // 4096

// Scratch for deterministic single-kernel reduction (no device allocation allowed)
__device__ float g_partials[NBLOCKS];
__device__ unsigned int g_done_count;   // zero-init at load; last block resets each launch

// Numerically stable log-sigmoid: logsig(x) = min(x,0) - log1p(exp(-|x|))
__device__ __forceinline__ float log_sigmoid(float x) {
    return fminf(x, 0.0f) - log1pf(__expf(-fabsf(x)));
}

__global__ void __launch_bounds__(THREADS)
skipgram_fused_kernel(const int* __restrict__ input_idx,
                      const int* __restrict__ output_idx,
                      const int* __restrict__ neg_idx,
                      const float* __restrict__ W_in,
                      const float* __restrict__ W_out,
                      float* __restrict__ out)
{
    const int warp = threadIdx.x >> 5;
    const int lane = threadIdx.x & 31;
    const int s = blockIdx.x * WARPS_PER_BLOCK + warp;   // sample id

    const float4* __restrict__ Win4  = reinterpret_cast<const float4*>(W_in);
    const float4* __restrict__ Wout4 = reinterpret_cast<const float4*>(W_out);

    // Indices: uniform broadcast loads for in/out; lanes 0..9 carry neg indices
    const int ii = __ldg(input_idx  + s);
    const int oi = __ldg(output_idx + s);
    const int nlane = (lane < K_NEG) ? lane : 0;
    const int ni = __ldg(neg_idx + (size_t)s * K_NEG + nlane);

    // Broadcast all neg indices up front so the 10 row loads have no
    // serializing dependency -> ptxas front-batches all LDG.128s (max MLP).
    int nidx[K_NEG];
    #pragma unroll
    for (int k = 0; k < K_NEG; k++)
        nidx[k] = __shfl_sync(0xffffffffu, ni, k);

    // Row slice per lane: 128 dims = 32 lanes x float4 (512B coalesced row)
    const float4 a = __ldg(Win4  + (size_t)ii * 32 + lane);
    const float4 b = __ldg(Wout4 + (size_t)oi * 32 + lane);

    float4 c[K_NEG];
    #pragma unroll
    for (int k = 0; k < K_NEG; k++)
        c[k] = __ldg(Wout4 + (size_t)nidx[k] * 32 + lane);

    float dots[K_NEG + 1];
    dots[0] = a.x * b.x + a.y * b.y + a.z * b.z + a.w * b.w;
    #pragma unroll
    for (int k = 0; k < K_NEG; k++)
        dots[k + 1] = a.x * c[k].x + a.y * c[k].y + a.z * c[k].z + a.w * c[k].w;

    // Warp-reduce all 11 dot partials
    #pragma unroll
    for (int j = 0; j < K_NEG + 1; j++) {
        #pragma unroll
        for (int off = 16; off > 0; off >>= 1)
            dots[j] += __shfl_xor_sync(0xffffffffu, dots[j], off);
    }

    __shared__ float warp_sums[WARPS_PER_BLOCK];
    if (lane == 0) {
        float loss = log_sigmoid(dots[0]);
        #pragma unroll
        for (int k = 0; k < K_NEG; k++)
            loss += log_sigmoid(-dots[k + 1]);
        warp_sums[warp] = loss;
    }
    __syncthreads();

    // Deterministic in-block reduction (fixed order, thread 0) + arrival mark
    __shared__ bool is_last;
    if (threadIdx.x == 0) {
        float bsum = 0.0f;
        #pragma unroll
        for (int w = 0; w < WARPS_PER_BLOCK; w++) bsum += warp_sums[w];
        g_partials[blockIdx.x] = bsum;
        __threadfence();                      // publish partial before counting
        unsigned int t = atomicAdd(&g_done_count, 1u);
        is_last = (t == NBLOCKS - 1);
    }
    __syncthreads();

    // Last block performs the fixed-order final reduction (deterministic)
    if (is_last) {
        __shared__ double sh[THREADS];
        const int tid = threadIdx.x;
        double acc = 0.0;
        for (int i = tid; i < NBLOCKS; i += THREADS)   // fixed strided order
            acc += (double)g_partials[i];
        sh[tid] = acc;
        __syncthreads();
        for (int off = THREADS / 2; off > 0; off >>= 1) {
            if (tid < off) sh[tid] += sh[tid + off];
            __syncthreads();
        }
        if (tid == 0) {
            out[0] = (float)(sh[0] / (double)N_SAMPLES);
            g_done_count = 0;                 // reset for next graph replay
        }
    }
}

extern "C" void kernel_launch(void* const* d_in, const int* in_sizes, int n_in,
                              void* d_out, int out_size)
{
    const int*   input_idx  = (const int*)  d_in[0];
    const int*   output_idx = (const int*)  d_in[1];
    const int*   neg_idx    = (const int*)  d_in[2];
    const float* W_in       = (const float*)d_in[3];
    const float* W_out      = (const float*)d_in[4];
    float*       out        = (float*)d_out;

    skipgram_fused_kernel<<<NBLOCKS, THREADS>>>(input_idx, output_idx, neg_idx,
                                                W_in, W_out, out);
}

// round 10
// speedup vs baseline: 1.2385x; 1.2385x over previous
#include <cuda_runtime.h>
#include <cuda_bf16.h>

// Problem constants (from reference)
#define N_SAMPLES 65536
#define N_DIMS    128
#define K_NEG     10

constexpr int LANES_PER_SAMPLE = 8;                      // 3 shuffle stages
constexpr int SAMPLES_PER_WARP = 32 / LANES_PER_SAMPLE;  // 4
constexpr int WARPS_PER_BLOCK  = 8;
constexpr int THREADS          = WARPS_PER_BLOCK * 32;   // 256
constexpr int SAMPLES_PER_BLOCK = WARPS_PER_BLOCK * SAMPLES_PER_WARP;  // 32
constexpr int NBLOCKS = N_SAMPLES / SAMPLES_PER_BLOCK;   // 2048

// Scratch for deterministic single-kernel reduction (no device allocation allowed)
__device__ float g_partials[NBLOCKS];
__device__ unsigned int g_done_count;   // zero at load; last block resets each launch

// Numerically stable log-sigmoid: logsig(x) = min(x,0) - log1p(exp(-|x|))
__device__ __forceinline__ float log_sigmoid(float x) {
    return fminf(x, 0.0f) - log1pf(__expf(-fabsf(x)));
}

__device__ __forceinline__ float dot4(const float4 a, const float4 c) {
    return a.x * c.x + a.y * c.y + a.z * c.z + a.w * c.w;
}

__global__ void __launch_bounds__(THREADS, 2)
skipgram_fused_kernel(const int* __restrict__ input_idx,
                      const int* __restrict__ output_idx,
                      const int* __restrict__ neg_idx,
                      const float* __restrict__ W_in,
                      const float* __restrict__ W_out,
                      float* __restrict__ out)
{
    const int warp  = threadIdx.x >> 5;
    const int lane  = threadIdx.x & 31;
    const int group = lane >> 3;          // 0..3  (sample within warp)
    const int sub   = lane & 7;           // 0..7  (slice within sample)
    const int s = blockIdx.x * SAMPLES_PER_BLOCK + warp * SAMPLES_PER_WARP + group;

    const float4* __restrict__ Win4  = reinterpret_cast<const float4*>(W_in);
    const float4* __restrict__ Wout4 = reinterpret_cast<const float4*>(W_out);

    const int ii = __ldg(input_idx  + s);
    const int oi = __ldg(output_idx + s);

    // All neg indices up front -> no serializing dependency before the row loads
    int nidx[K_NEG];
    #pragma unroll
    for (int k = 0; k < K_NEG; k++)
        nidx[k] = __ldg(neg_idx + (size_t)s * K_NEG + k);

    // Each lane owns a 16-float slice of the 128-dim row, interleaved stride-8:
    // float4 index = sub + j*8  -> each warp load instr = 4 x 128B contiguous segs.
    const float4* arow = Win4  + (size_t)ii * 32;
    const float4* brow = Wout4 + (size_t)oi * 32;

    float4 a[4], b[4];
    #pragma unroll
    for (int j = 0; j < 4; j++) a[j] = __ldg(arow + sub + j * 8);
    #pragma unroll
    for (int j = 0; j < 4; j++) b[j] = __ldg(brow + sub + j * 8);

    float vals[K_NEG + 1];
    {
        float d = 0.0f;
        #pragma unroll
        for (int j = 0; j < 4; j++) d += dot4(a[j], b[j]);
        vals[0] = d;
    }

    #pragma unroll
    for (int k = 0; k < K_NEG; k++) {
        const float4* crow = Wout4 + (size_t)nidx[k] * 32;
        float4 c[4];
        #pragma unroll
        for (int j = 0; j < 4; j++) c[j] = __ldg(crow + sub + j * 8);
        float d = 0.0f;
        #pragma unroll
        for (int j = 0; j < 4; j++) d += dot4(a[j], c[j]);
        vals[k + 1] = d;
    }

    // Reduce across the 8 lanes of each sample group (xor<8 stays in-group)
    #pragma unroll
    for (int j = 0; j < K_NEG + 1; j++) {
        #pragma unroll
        for (int off = 4; off > 0; off >>= 1)
            vals[j] += __shfl_xor_sync(0xffffffffu, vals[j], off);
    }

    __shared__ float sample_loss[SAMPLES_PER_BLOCK];
    if (sub == 0) {
        float loss = log_sigmoid(vals[0]);
        #pragma unroll
        for (int k = 0; k < K_NEG; k++)
            loss += log_sigmoid(-vals[k + 1]);
        sample_loss[warp * SAMPLES_PER_WARP + group] = loss;
    }
    __syncthreads();

    // Deterministic in-block reduction (fixed order, thread 0) + arrival mark
    __shared__ bool is_last;
    if (threadIdx.x == 0) {
        float bsum = 0.0f;
        #pragma unroll
        for (int i = 0; i < SAMPLES_PER_BLOCK; i++) bsum += sample_loss[i];
        g_partials[blockIdx.x] = bsum;
        __threadfence();                      // publish partial before counting
        unsigned int t = atomicAdd(&g_done_count, 1u);
        is_last = (t == NBLOCKS - 1);
    }
    __syncthreads();

    // Last block: fixed-order final reduction in double (deterministic)
    if (is_last) {
        __shared__ double sh[THREADS];
        const int tid = threadIdx.x;
        double acc = 0.0;
        for (int i = tid; i < NBLOCKS; i += THREADS)   // fixed strided order
            acc += (double)g_partials[i];
        sh[tid] = acc;
        __syncthreads();
        for (int off = THREADS / 2; off > 0; off >>= 1) {
            if (tid < off) sh[tid] += sh[tid + off];
            __syncthreads();
        }
        if (tid == 0) {
            out[0] = (float)(sh[0] / (double)N_SAMPLES);
            g_done_count = 0;                 // reset for next graph replay
        }
    }
}

extern "C" void kernel_launch(void* const* d_in, const int* in_sizes, int n_in,
                              void* d_out, int out_size)
{
    const int*   input_idx  = (const int*)  d_in[0];
    const int*   output_idx = (const int*)  d_in[1];
    const int*   neg_idx    = (const int*)  d_in[2];
    const float* W_in       = (const float*)d_in[3];
    const float* W_out      = (const float*)d_in[4];
    float*       out        = (float*)d_out;

    skipgram_fused_kernel<<<NBLOCKS, THREADS>>>(input_idx, output_idx, neg_idx,
                                                W_in, W_out, out);
}